// round 1
// baseline (speedup 1.0000x reference)
#include <cuda_runtime.h>

// ConvTranspose2d: x(16,256,64,64) fp32, w(256,128,4,4), bias(128)
// stride=2, padding=1 -> out(16,128,128,128)
//
// Parity decomposition: for output (oy,ox) with oy=2y+py, ox=2x+px:
//   exactly 2 valid ky (= 3-py, 1-py, reading input rows y-1+py, y+py)
//   and 2 valid kx (= 3-px, 1-px, reading input cols x-1+px, x+px).
// So each parity class is a 2x2-tap conv over the 64x64 input, K = 4*256.

#define CI 16

// Pre-transposed weights: [parity(4)][ci(256)][tap(4)][co(128)]
__device__ float g_wT[4 * 256 * 4 * 128];

__global__ void wt_kernel(const float* __restrict__ w) {
    int idx = blockIdx.x * blockDim.x + threadIdx.x;
    if (idx >= 4 * 256 * 4 * 128) return;
    int co  = idx & 127;
    int t   = (idx >> 7) & 3;
    int ci  = (idx >> 9) & 255;
    int par = idx >> 17;
    int py = par >> 1, px = par & 1;
    int ri = t >> 1,  jx = t & 1;
    int ky = 3 - py - 2 * ri;
    int kx = 3 - px - 2 * jx;
    g_wT[idx] = w[((ci * 128 + co) * 4 + ky) * 4 + kx];
}

__global__ __launch_bounds__(256, 2)
void convt_kernel(const float* __restrict__ x,
                  const float* __restrict__ bias,
                  float* __restrict__ out) {
    // grid: x = 64 (class row y), y = 4 (parity), z = 16 (batch)
    const int y   = blockIdx.x;
    const int par = blockIdx.y;
    const int n   = blockIdx.z;
    const int py = par >> 1, px = par & 1;

    __shared__ float xs[2][CI][68];        // 2 input rows x CI cin x 66(+2 pad) cols
    __shared__ float ws[CI][4][128];       // CI cin x 4 taps x 128 cout

    const int tid = threadIdx.x;
    const int tx  = tid & 15;              // pixel group: px positions [tx*4, tx*4+4)
    const int ty  = tid >> 4;              // cout group:  [ty*8, ty*8+8)

    float acc[4][8];
#pragma unroll
    for (int p = 0; p < 4; p++)
#pragma unroll
        for (int q = 0; q < 8; q++) acc[p][q] = 0.0f;

    const int r0 = y - 1 + py;             // input rows r0, r0+1
    const float* xbase = x + (size_t)n * 256 * 4096;

    for (int cc = 0; cc < 256; cc += CI) {
        // ---- stage weights (fully coalesced from g_wT) ----
        const float* wsrc = g_wT + ((size_t)par * 256 + cc) * 512;  // 4*128 per ci
        float* wdst = (float*)ws;
#pragma unroll
        for (int i = 0; i < (CI * 4 * 128) / 256; i++)
            wdst[tid + i * 256] = wsrc[tid + i * 256];

        // ---- stage x: 2 rows x CI ci x 66 cols (buffer col b -> ix = b-1) ----
        for (int e = tid; e < 2 * CI * 66; e += 256) {
            int col = e % 66;
            int rem = e / 66;
            int ci  = rem % CI;
            int ri  = rem / CI;
            int iy  = r0 + ri;
            int ix  = col - 1;
            float v = 0.0f;
            if (iy >= 0 && iy < 64 && ix >= 0 && ix < 64)
                v = xbase[(size_t)(cc + ci) * 4096 + iy * 64 + ix];
            xs[ri][ci][col] = v;
        }
        __syncthreads();

#pragma unroll 2
        for (int ci = 0; ci < CI; ci++) {
            // x values covering 4 pixels x 2 col-offsets: 5 per row
            float xr[2][5];
#pragma unroll
            for (int ri = 0; ri < 2; ri++)
#pragma unroll
                for (int j = 0; j < 5; j++)
                    xr[ri][j] = xs[ri][ci][tx * 4 + px + j];

#pragma unroll
            for (int t = 0; t < 4; t++) {
                const float4* wv = (const float4*)&ws[ci][t][ty * 8];
                float4 w0 = wv[0];
                float4 w1 = wv[1];
                const int ri = t >> 1, jx = t & 1;
#pragma unroll
                for (int p = 0; p < 4; p++) {
                    float xv = xr[ri][p + jx];
                    acc[p][0] = fmaf(xv, w0.x, acc[p][0]);
                    acc[p][1] = fmaf(xv, w0.y, acc[p][1]);
                    acc[p][2] = fmaf(xv, w0.z, acc[p][2]);
                    acc[p][3] = fmaf(xv, w0.w, acc[p][3]);
                    acc[p][4] = fmaf(xv, w1.x, acc[p][4]);
                    acc[p][5] = fmaf(xv, w1.y, acc[p][5]);
                    acc[p][6] = fmaf(xv, w1.z, acc[p][6]);
                    acc[p][7] = fmaf(xv, w1.w, acc[p][7]);
                }
            }
        }
        __syncthreads();
    }

    // ---- epilogue: out[n][co][2y+py][2x+px] ----
    const int oy = 2 * y + py;
#pragma unroll
    for (int q = 0; q < 8; q++) {
        const int co = ty * 8 + q;
        const float b = __ldg(&bias[co]);
        float* obase = out + (((size_t)n * 128 + co) * 128 + oy) * 128;
#pragma unroll
        for (int p = 0; p < 4; p++) {
            const int ox = 2 * (tx * 4 + p) + px;
            obase[ox] = acc[p][q] + b;
        }
    }
}

extern "C" void kernel_launch(void* const* d_in, const int* in_sizes, int n_in,
                              void* d_out, int out_size) {
    const float* x    = (const float*)d_in[0];
    const float* w    = (const float*)d_in[1];
    const float* bias = (const float*)d_in[2];
    float* out        = (float*)d_out;

    wt_kernel<<<(4 * 256 * 4 * 128 + 255) / 256, 256>>>(w);

    dim3 grid(64, 4, 16);
    convt_kernel<<<grid, 256>>>(x, bias, out);
}

// round 2
// speedup vs baseline: 1.0426x; 1.0426x over previous
#include <cuda_runtime.h>

// ConvTranspose2d: x(16,256,64,64) fp32, w(256,128,4,4), bias(128)
// stride=2, padding=1 -> out(16,128,128,128)
//
// Parity decomposition: each output parity class (py,px) is a 2x2-tap conv.
// R2: packed fp32 math (fma.rn.f32x2) — 2 MACs per issue slot, packed over
// Cout pairs (weights contiguous in Cout), x broadcast-packed {xv,xv}.

#define CI 16

// Pre-transposed weights: [parity(4)][ci(256)][tap(4)][co(128)]
__device__ float g_wT[4 * 256 * 4 * 128];

__global__ void wt_kernel(const float* __restrict__ w) {
    int idx = blockIdx.x * blockDim.x + threadIdx.x;
    if (idx >= 4 * 256 * 4 * 128) return;
    int co  = idx & 127;
    int t   = (idx >> 7) & 3;
    int ci  = (idx >> 9) & 255;
    int par = idx >> 17;
    int py = par >> 1, px = par & 1;
    int ri = t >> 1,  jx = t & 1;
    int ky = 3 - py - 2 * ri;
    int kx = 3 - px - 2 * jx;
    g_wT[idx] = w[((ci * 128 + co) * 4 + ky) * 4 + kx];
}

// packed-f32x2 helpers
__device__ __forceinline__ unsigned long long pack2(float v) {
    unsigned long long r;
    asm("mov.b64 %0, {%1, %1};" : "=l"(r) : "f"(v));
    return r;
}
__device__ __forceinline__ void ffma2(unsigned long long& d,
                                      unsigned long long a,
                                      unsigned long long b) {
    asm("fma.rn.f32x2 %0, %1, %2, %0;" : "+l"(d) : "l"(a), "l"(b));
}

__global__ __launch_bounds__(256, 2)
void convt_kernel(const float* __restrict__ x,
                  const float* __restrict__ bias,
                  float* __restrict__ out) {
    // grid: x = 64 (class row y), y = 4 (parity), z = 16 (batch)
    const int y   = blockIdx.x;
    const int par = blockIdx.y;
    const int n   = blockIdx.z;
    const int py = par >> 1, px = par & 1;

    __shared__ __align__(16) float xs[2][CI][68];   // 2 rows x CI cin x 66(+2) cols
    __shared__ __align__(16) float ws[CI][4][128];  // CI cin x 4 taps x 128 cout

    const int tid = threadIdx.x;
    const int tx  = tid & 15;              // pixel group: px positions [tx*4, tx*4+4)
    const int ty  = tid >> 4;              // cout group:  [ty*8, ty*8+8)

    // acc[pixel][cout-pair], each f32x2 = (co=2c, co=2c+1)
    unsigned long long acc[4][4];
#pragma unroll
    for (int p = 0; p < 4; p++)
#pragma unroll
        for (int c = 0; c < 4; c++) acc[p][c] = 0ULL;

    const int r0 = y - 1 + py;             // input rows r0, r0+1
    const float* xbase = x + (size_t)n * 256 * 4096;

    for (int cc = 0; cc < 256; cc += CI) {
        // ---- stage weights (coalesced from g_wT) ----
        const float* wsrc = g_wT + ((size_t)par * 256 + cc) * 512;  // 4*128 per ci
        float* wdst = (float*)ws;
#pragma unroll
        for (int i = 0; i < (CI * 4 * 128) / 256; i++)
            wdst[tid + i * 256] = wsrc[tid + i * 256];

        // ---- stage x: 2 rows x CI ci x 66 cols (buffer col b -> ix = b-1) ----
        for (int e = tid; e < 2 * CI * 66; e += 256) {
            int col = e % 66;
            int rem = e / 66;
            int ci  = rem % CI;
            int ri  = rem / CI;
            int iy  = r0 + ri;
            int ix  = col - 1;
            float v = 0.0f;
            if (iy >= 0 && iy < 64 && ix >= 0 && ix < 64)
                v = xbase[(size_t)(cc + ci) * 4096 + iy * 64 + ix];
            xs[ri][ci][col] = v;
        }
        __syncthreads();

#pragma unroll 2
        for (int ci = 0; ci < CI; ci++) {
            // x values covering 4 pixels x 2 col-offsets: 5 per row, pre-packed
            unsigned long long xp[2][5];
#pragma unroll
            for (int ri = 0; ri < 2; ri++)
#pragma unroll
                for (int j = 0; j < 5; j++)
                    xp[ri][j] = pack2(xs[ri][ci][tx * 4 + px + j]);

#pragma unroll
            for (int t = 0; t < 4; t++) {
                // 8 cout = 4 packed pairs, via two 16B smem loads
                const ulonglong2* wv = (const ulonglong2*)&ws[ci][t][ty * 8];
                ulonglong2 wa = wv[0];
                ulonglong2 wb = wv[1];
                const int ri = t >> 1, jx = t & 1;
#pragma unroll
                for (int p = 0; p < 4; p++) {
                    unsigned long long xv = xp[ri][p + jx];
                    ffma2(acc[p][0], xv, wa.x);
                    ffma2(acc[p][1], xv, wa.y);
                    ffma2(acc[p][2], xv, wb.x);
                    ffma2(acc[p][3], xv, wb.y);
                }
            }
        }
        __syncthreads();
    }

    // ---- epilogue: out[n][co][2y+py][2x+px] ----
    const int oy = 2 * y + py;
#pragma unroll
    for (int c = 0; c < 4; c++) {
#pragma unroll
        for (int h = 0; h < 2; h++) {
            const int co = ty * 8 + c * 2 + h;
            const float b = __ldg(&bias[co]);
            float* obase = out + (((size_t)n * 128 + co) * 128 + oy) * 128;
#pragma unroll
            for (int p = 0; p < 4; p++) {
                const int ox = 2 * (tx * 4 + p) + px;
                float2 v = *(float2*)&acc[p][c];
                obase[ox] = (h == 0 ? v.x : v.y) + b;
            }
        }
    }
}

extern "C" void kernel_launch(void* const* d_in, const int* in_sizes, int n_in,
                              void* d_out, int out_size) {
    const float* x    = (const float*)d_in[0];
    const float* w    = (const float*)d_in[1];
    const float* bias = (const float*)d_in[2];
    float* out        = (float*)d_out;

    wt_kernel<<<(4 * 256 * 4 * 128 + 255) / 256, 256>>>(w);

    dim3 grid(64, 4, 16);
    convt_kernel<<<grid, 256>>>(x, bias, out);
}

// round 4
// speedup vs baseline: 1.5353x; 1.4726x over previous
#include <cuda_runtime.h>
#include <cuda_bf16.h>
#include <cstdint>

// ConvTranspose2d x(16,256,64,64) w(256,128,4,4) b(128) s=2 p=1 -> (16,128,128,128)
// Parity-class GEMM: D[pix=128, co=128] = A[pix, K=1024] * B[co, K]^T
// bf16 hi/lo split (hh + hl + lh) with fp32 accumulation, via ldmatrix + mma.sync
// (portable HMMA path; tcgen05 is unavailable at the sm_103 base target).

#define NCHUNK 16
#define OFF_BH 0
#define OFF_BL 16384
#define OFF_AH 32768
#define OFF_AL 49152
#define OFF_XS 65536                 // float[16*3*68] = 13056 B
#define SMEM_BYTES (65536 + 13056)

// Pre-transposed weights: [par][chunk][part(hi,lo)][co(128) x 64 bf16 k'], SW128-swizzled rows
__device__ __align__(1024) unsigned char g_wB[4][NCHUNK][2][16384];

__global__ void prep_wB(const float* __restrict__ w) {
    int idx = blockIdx.x * blockDim.x + threadIdx.x;
    if (idx >= (1 << 20)) return;
    int kq    = idx & 63;
    int co    = (idx >> 6) & 127;
    int part  = (idx >> 13) & 1;
    int chunk = (idx >> 14) & 15;
    int par   = idx >> 18;
    int py = par >> 1, px = par & 1;
    int cil = kq >> 2, ri = (kq >> 1) & 1, jx = kq & 1;
    int ci = chunk * 16 + cil;
    int ky = 3 - py - 2 * ri;
    int kx = 3 - px - 2 * jx;
    float v = w[((ci * 128 + co) * 4 + ky) * 4 + kx];
    __nv_bfloat16 hi = __float2bfloat16(v);
    __nv_bfloat16 outv = (part == 0) ? hi : __float2bfloat16(v - __bfloat162float(hi));
    uint32_t off = (uint32_t)co * 128 + (uint32_t)kq * 2;
    uint32_t sw = off ^ ((off >> 3) & 0x70);
    *(__nv_bfloat16*)(&g_wB[par][chunk][part][sw]) = outv;
}

__device__ __forceinline__ uint32_t smem_u32(const void* p) {
    uint32_t a;
    asm("{ .reg .u64 t; cvta.to.shared.u64 t, %1; cvt.u32.u64 %0, t; }" : "=r"(a) : "l"(p));
    return a;
}
__device__ __forceinline__ void ldsm4(uint32_t& r0, uint32_t& r1, uint32_t& r2, uint32_t& r3,
                                      uint32_t addr) {
    asm volatile("ldmatrix.sync.aligned.m8n8.x4.shared.b16 {%0,%1,%2,%3}, [%4];"
                 : "=r"(r0), "=r"(r1), "=r"(r2), "=r"(r3) : "r"(addr));
}
__device__ __forceinline__ void mma16816(float* c, uint32_t a0, uint32_t a1, uint32_t a2,
                                         uint32_t a3, uint32_t b0, uint32_t b1) {
    asm volatile(
        "mma.sync.aligned.m16n8k16.row.col.f32.bf16.bf16.f32 "
        "{%0,%1,%2,%3}, {%4,%5,%6,%7}, {%8,%9}, {%0,%1,%2,%3};"
        : "+f"(c[0]), "+f"(c[1]), "+f"(c[2]), "+f"(c[3])
        : "r"(a0), "r"(a1), "r"(a2), "r"(a3), "r"(b0), "r"(b1));
}

__global__ __launch_bounds__(256, 2)
void convt_mma(const float* __restrict__ x,
               const float* __restrict__ bias,
               float* __restrict__ out) {
    extern __shared__ char sm[];
    const int tid = threadIdx.x;
    const int l   = tid & 31;
    const int w   = tid >> 5;
    const int warp_m = w >> 2;           // 0..1 (64-pixel half)
    const int warp_n = w & 3;            // 0..3 (32-cout slice)
    const int yt  = blockIdx.x;          // 32 row-pair tiles
    const int par = blockIdx.y;          // 4
    const int n   = blockIdx.z;          // 16
    const int py = par >> 1, px = par & 1;

    const uint32_t smb = smem_u32(sm);
    float* XS = (float*)(sm + OFF_XS);

    float acc[4][4][4];
#pragma unroll
    for (int mi = 0; mi < 4; mi++)
#pragma unroll
        for (int nj = 0; nj < 4; nj++)
#pragma unroll
            for (int q = 0; q < 4; q++) acc[mi][nj][q] = 0.0f;

    // per-lane ldmatrix row params
    const int arow_off = (l & 7) + ((l >> 3) & 1) * 8;   // A: m sub-row
    const int ahalf    = l >> 4;                          // A: k half (8)
    const int brow_off = (l & 7) + (l >> 4) * 8;          // B: n sub-row
    const int bhalf    = (l >> 3) & 1;                    // B: k half (8)

    const int R = 2 * yt - 1 + py;                        // input rows R..R+2
    const float* xb = x + (size_t)n * 256 * 4096;

    // A-build mapping: thread -> (pixel, k-half-of-64)
    const int ap  = tid >> 1;            // pixel 0..127
    const int akh = tid & 1;             // cil range [akh*8, akh*8+8)
    const int arp = ap >> 6, ax2 = ap & 63;
    const int ac0 = ax2 + px;
    const uint32_t a_xorm = (uint32_t)(ap & 7) << 4;
    const uint32_t a_base = (uint32_t)ap * 128;

    for (int c = 0; c < NCHUNK; c++) {
        // ---- stage B (flat copy of pre-swizzled hi+lo tiles, 32KB) ----
        {
            const float4* src = (const float4*)g_wB[par][c];
            float4* dst = (float4*)(sm + OFF_BH);
#pragma unroll
            for (int i = 0; i < 8; i++) dst[tid + i * 256] = src[tid + i * 256];
        }
        // ---- stage xs: 16 ci x 3 rows x 66 cols ----
        for (int e = tid; e < 16 * 3 * 66; e += 256) {
            int col = e % 66;
            int rem = e / 66;
            int r   = rem % 3;
            int cil = rem / 3;
            int iy = R + r, ix = col - 1;
            float v = 0.0f;
            if (iy >= 0 && iy < 64 && ix >= 0 && ix < 64)
                v = xb[((size_t)(c * 16 + cil) << 12) + (iy << 6) + ix];
            XS[(cil * 3 + r) * 68 + col] = v;
        }
        __syncthreads();

        // ---- A build: im2col -> bf16 hi/lo, swizzled smem ----
#pragma unroll
        for (int q = 0; q < 8; q++) {
            const int cil = akh * 8 + q;
#pragma unroll
            for (int ri = 0; ri < 2; ri++) {
                const float* row = XS + (cil * 3 + arp + ri) * 68;
                float v0 = row[ac0];
                float v1 = row[ac0 + 1];
                uint32_t hp;
                asm("cvt.rn.bf16x2.f32 %0, %1, %2;" : "=r"(hp) : "f"(v1), "f"(v0));
                float h0, h1;
                asm("{ .reg .b16 lo,hi; mov.b32 {lo,hi}, %2; cvt.f32.bf16 %0, lo; cvt.f32.bf16 %1, hi; }"
                    : "=f"(h0), "=f"(h1) : "r"(hp));
                float l0 = v0 - h0, l1 = v1 - h1;
                uint32_t lp;
                asm("cvt.rn.bf16x2.f32 %0, %1, %2;" : "=r"(lp) : "f"(l1), "f"(l0));
                const uint32_t kb = (uint32_t)(cil * 2 + ri) * 4;
                const uint32_t ao = a_base + (kb ^ a_xorm);
                *(uint32_t*)(sm + OFF_AH + ao) = hp;
                *(uint32_t*)(sm + OFF_AL + ao) = lp;
            }
        }
        __syncthreads();

        // ---- MMA: 3 passes (A_hi*B_hi, A_hi*B_lo, A_lo*B_hi) ----
#pragma unroll
        for (int pass = 0; pass < 3; pass++) {
            const uint32_t Ab = smb + (pass == 2 ? OFF_AL : OFF_AH);
            const uint32_t Bb = smb + (pass == 1 ? OFF_BL : OFF_BH);
#pragma unroll
            for (int ks = 0; ks < 4; ks++) {
                uint32_t a[4][4];
#pragma unroll
                for (int mi = 0; mi < 4; mi++) {
                    const int row = warp_m * 64 + mi * 16 + arow_off;
                    const uint32_t kb = (uint32_t)(ks * 32 + ahalf * 16);
                    const uint32_t addr =
                        Ab + (uint32_t)row * 128 + (kb ^ (((uint32_t)row & 7) << 4));
                    ldsm4(a[mi][0], a[mi][1], a[mi][2], a[mi][3], addr);
                }
                uint32_t b[4][2];
#pragma unroll
                for (int bi = 0; bi < 2; bi++) {
                    const int row = warp_n * 32 + bi * 16 + brow_off;
                    const uint32_t kb = (uint32_t)(ks * 32 + bhalf * 16);
                    const uint32_t addr =
                        Bb + (uint32_t)row * 128 + (kb ^ (((uint32_t)row & 7) << 4));
                    uint32_t r0, r1, r2, r3;
                    ldsm4(r0, r1, r2, r3, addr);
                    b[bi * 2][0] = r0;     b[bi * 2][1] = r1;
                    b[bi * 2 + 1][0] = r2; b[bi * 2 + 1][1] = r3;
                }
#pragma unroll
                for (int mi = 0; mi < 4; mi++)
#pragma unroll
                    for (int nj = 0; nj < 4; nj++)
                        mma16816(acc[mi][nj], a[mi][0], a[mi][1], a[mi][2], a[mi][3],
                                 b[nj][0], b[nj][1]);
            }
        }
        __syncthreads();
    }

    // ---- epilogue: acc -> out[n][co][oy][ox] + bias ----
    const int prow = l >> 2;
    const int pcol = (l & 3) * 2;
#pragma unroll
    for (int nj = 0; nj < 4; nj++) {
        const int co0 = warp_n * 32 + nj * 8 + pcol;
        const float b0 = __ldg(&bias[co0]);
        const float b1 = __ldg(&bias[co0 + 1]);
        float* o0 = out + ((size_t)(n * 128 + co0) << 14);
        float* o1 = out + ((size_t)(n * 128 + co0 + 1) << 14);
#pragma unroll
        for (int mi = 0; mi < 4; mi++) {
#pragma unroll
            for (int h = 0; h < 2; h++) {
                const int pix = warp_m * 64 + mi * 16 + prow + h * 8;
                const int oy = 2 * (2 * yt + (pix >> 6)) + py;
                const int ox = 2 * (pix & 63) + px;
                const int off = (oy << 7) + ox;
                o0[off] = acc[mi][nj][h * 2 + 0] + b0;
                o1[off] = acc[mi][nj][h * 2 + 1] + b1;
            }
        }
    }
}

extern "C" void kernel_launch(void* const* d_in, const int* in_sizes, int n_in,
                              void* d_out, int out_size) {
    const float* x    = (const float*)d_in[0];
    const float* w    = (const float*)d_in[1];
    const float* bias = (const float*)d_in[2];
    float* out        = (float*)d_out;

    cudaFuncSetAttribute(convt_mma, cudaFuncAttributeMaxDynamicSharedMemorySize, SMEM_BYTES);

    prep_wB<<<(1 << 20) / 256, 256>>>(w);

    dim3 grid(32, 4, 16);
    convt_mma<<<grid, 256, SMEM_BYTES>>>(x, bias, out);
}

// round 5
// speedup vs baseline: 3.0252x; 1.9705x over previous
#include <cuda_runtime.h>
#include <cuda_bf16.h>
#include <cstdint>

// ConvTranspose2d x(16,256,64,64) w(256,128,4,4) b(128) s=2 p=1 -> (16,128,128,128)
// Parity-class GEMM: D[pix=128, co=128] = A[pix, K=1024] * B[co, K]^T
// bf16 hi/lo split (hh + hl + lh), fp32 accum, ldmatrix + mma.sync.
// R5: cp.async staging (precomputed descriptors, zfill), XS double-buffer
// prefetch, truncation-based split via prmt, fragment-reuse MMA loop.

#define NCHUNK 16
#define OFF_B  0                       // 32768: [hi 16K | lo 16K], pre-swizzled
#define OFF_AH 32768
#define OFF_AL 49152
#define OFF_XS 65536                   // 2 x 13824B: [cil16][r3][72 floats]
#define XS_ROW 72
#define XS_BUF_B 13824
#define SMEM_BYTES (65536 + 2 * XS_BUF_B)

__device__ __align__(1024) unsigned char g_wB[4][NCHUNK][2][16384];

__global__ void prep_wB(const float* __restrict__ w) {
    int idx = blockIdx.x * blockDim.x + threadIdx.x;
    if (idx >= (1 << 20)) return;
    int kq    = idx & 63;
    int co    = (idx >> 6) & 127;
    int part  = (idx >> 13) & 1;
    int chunk = (idx >> 14) & 15;
    int par   = idx >> 18;
    int py = par >> 1, px = par & 1;
    int cil = kq >> 2, ri = (kq >> 1) & 1, jx = kq & 1;
    int ci = chunk * 16 + cil;
    int ky = 3 - py - 2 * ri;
    int kx = 3 - px - 2 * jx;
    float v = w[((ci * 128 + co) * 4 + ky) * 4 + kx];
    __nv_bfloat16 hi = __float2bfloat16(v);
    __nv_bfloat16 outv = (part == 0) ? hi : __float2bfloat16(v - __bfloat162float(hi));
    uint32_t off = (uint32_t)co * 128 + (uint32_t)kq * 2;
    uint32_t sw = off ^ ((off >> 3) & 0x70);
    *(__nv_bfloat16*)(&g_wB[par][chunk][part][sw]) = outv;
}

__device__ __forceinline__ uint32_t smem_u32(const void* p) {
    uint32_t a;
    asm("{ .reg .u64 t; cvta.to.shared.u64 t, %1; cvt.u32.u64 %0, t; }" : "=r"(a) : "l"(p));
    return a;
}
__device__ __forceinline__ void cp16(uint32_t dst, const void* src, uint32_t srcsz) {
    asm volatile("cp.async.cg.shared.global [%0], [%1], 16, %2;"
                 :: "r"(dst), "l"(src), "r"(srcsz) : "memory");
}
__device__ __forceinline__ void ldsm4(uint32_t& r0, uint32_t& r1, uint32_t& r2, uint32_t& r3,
                                      uint32_t addr) {
    asm volatile("ldmatrix.sync.aligned.m8n8.x4.shared.b16 {%0,%1,%2,%3}, [%4];"
                 : "=r"(r0), "=r"(r1), "=r"(r2), "=r"(r3) : "r"(addr));
}
__device__ __forceinline__ void mma16816(float* c, const uint32_t* a, const uint32_t* b) {
    asm volatile(
        "mma.sync.aligned.m16n8k16.row.col.f32.bf16.bf16.f32 "
        "{%0,%1,%2,%3}, {%4,%5,%6,%7}, {%8,%9}, {%0,%1,%2,%3};"
        : "+f"(c[0]), "+f"(c[1]), "+f"(c[2]), "+f"(c[3])
        : "r"(a[0]), "r"(a[1]), "r"(a[2]), "r"(a[3]), "r"(b[0]), "r"(b[1]));
}

__global__ __launch_bounds__(256, 2)
void convt_mma(const float* __restrict__ x,
               const float* __restrict__ bias,
               float* __restrict__ out) {
    extern __shared__ char sm[];
    const int tid = threadIdx.x;
    const int l   = tid & 31;
    const int w   = tid >> 5;
    const int warp_m = w >> 2;
    const int warp_n = w & 3;
    const int yt  = blockIdx.x;
    const int par = blockIdx.y;
    const int n   = blockIdx.z;
    const int py = par >> 1, px = par & 1;

    const uint32_t smb = smem_u32(sm);
    float* XS0 = (float*)(sm + OFF_XS);

    // ---- prezero XS pad cols (both buffers): cols 0-3 and 68-71 ----
    for (int e = tid; e < 192; e += 256) {
        int side = e & 1, t = e >> 1;
        int r = t % 3, rem = t / 3;
        int cil = rem & 15, buf = rem >> 4;
        float4* p = (float4*)(XS0 + buf * (XS_BUF_B / 4) + (cil * 3 + r) * XS_ROW + side * 68);
        *p = make_float4(0.f, 0.f, 0.f, 0.f);
    }

    float acc[4][4][4];
#pragma unroll
    for (int mi = 0; mi < 4; mi++)
#pragma unroll
        for (int nj = 0; nj < 4; nj++)
#pragma unroll
            for (int q = 0; q < 4; q++) acc[mi][nj][q] = 0.0f;

    const int arow_off = (l & 7) + ((l >> 3) & 1) * 8;
    const int ahalf    = l >> 4;
    const int brow_off = (l & 7) + (l >> 4) * 8;
    const int bhalf    = (l >> 3) & 1;

    const int R = 2 * yt - 1 + py;
    const float* xb = x + (size_t)n * 256 * 4096;

    // ---- precomputed XS cp.async descriptors (3 per thread) ----
    uint32_t xs_dst[3], xs_fill[3];
    const float* xs_src[3];
#pragma unroll
    for (int j = 0; j < 3; j++) {
        int e = tid + j * 256;
        int i16 = e & 15, t = e >> 4;
        int r = t % 3, cil = t / 3;
        int iy = R + r;
        bool valid = (iy >= 0 && iy < 64);
        xs_fill[j] = valid ? 16u : 0u;
        int iyc = valid ? iy : 0;
        xs_src[j] = xb + ((size_t)cil << 12) + (iyc << 6) + i16 * 4;
        xs_dst[j] = (uint32_t)(((cil * 3 + r) * XS_ROW + 4 + i16 * 4) * 4);
    }

    // A-build mapping: thread -> (pixel, interleaved cil half)
    const int ap  = tid >> 1;
    const int akh = tid & 1;
    const int arp = ap >> 6, ax2 = ap & 63;
    const int ac0 = ax2 + px + 3;
    const uint32_t a_xorm = (uint32_t)(ap & 7) << 4;
    const uint32_t a_base = (uint32_t)ap * 128;

    // ---- prefetch XS[0] ----
#pragma unroll
    for (int j = 0; j < 3; j++)
        cp16(smb + OFF_XS + xs_dst[j], xs_src[j], xs_fill[j]);
    asm volatile("cp.async.commit_group;" ::: "memory");

    for (int c = 0; c < NCHUNK; c++) {
        const int buf = c & 1;
        asm volatile("cp.async.wait_group 0;" ::: "memory");   // XS[c] ready
        __syncthreads();

        // ---- issue B[c] (group), then XS[c+1] (group) ----
        {
            const char* bsrc = (const char*)g_wB[par][c] + tid * 16;
            const uint32_t bdst = smb + OFF_B + (uint32_t)tid * 16;
#pragma unroll
            for (int i = 0; i < 8; i++)
                cp16(bdst + i * 4096, bsrc + i * 4096, 16);
            asm volatile("cp.async.commit_group;" ::: "memory");
        }
        if (c + 1 < NCHUNK) {
            const size_t coff = (size_t)(c + 1) << 16;
            const uint32_t dst0 = smb + OFF_XS + (buf ^ 1) * XS_BUF_B;
#pragma unroll
            for (int j = 0; j < 3; j++)
                cp16(dst0 + xs_dst[j], xs_src[j] + coff, xs_fill[j]);
        }
        asm volatile("cp.async.commit_group;" ::: "memory");

        // ---- A build: im2col -> bf16 hi(trunc)/lo, swizzled smem ----
        {
            const float* xsb = (const float*)(sm + OFF_XS + buf * XS_BUF_B);
#pragma unroll
            for (int q = 0; q < 8; q++) {
                const int cil = akh + 2 * q;
#pragma unroll
                for (int ri = 0; ri < 2; ri++) {
                    const float* row = xsb + (cil * 3 + arp + ri) * XS_ROW;
                    float v0 = row[ac0];
                    float v1 = row[ac0 + 1];
                    uint32_t u0 = __float_as_uint(v0), u1 = __float_as_uint(v1);
                    uint32_t hp;
                    asm("prmt.b32 %0, %1, %2, 0x7632;" : "=r"(hp) : "r"(u0), "r"(u1));
                    float h0 = __uint_as_float(u0 & 0xFFFF0000u);
                    float h1 = __uint_as_float(u1 & 0xFFFF0000u);
                    float l0 = v0 - h0, l1 = v1 - h1;
                    uint32_t lp;
                    asm("cvt.rn.bf16x2.f32 %0, %1, %2;" : "=r"(lp) : "f"(l1), "f"(l0));
                    const uint32_t ao = a_base + (((uint32_t)(cil * 2 + ri) * 4) ^ a_xorm);
                    *(uint32_t*)(sm + OFF_AH + ao) = hp;
                    *(uint32_t*)(sm + OFF_AL + ao) = lp;
                }
            }
        }
        asm volatile("cp.async.wait_group 1;" ::: "memory");   // B[c] ready
        __syncthreads();

        // ---- MMA: per ks load Ah,Bh,Bl -> hh+hl, reload Al -> lh ----
#pragma unroll
        for (int ks = 0; ks < 4; ks++) {
            uint32_t a[4][4], bh[4][2], bl[4][2];
            const uint32_t akb = (uint32_t)(ks * 32 + ahalf * 16);
#pragma unroll
            for (int mi = 0; mi < 4; mi++) {
                const int row = warp_m * 64 + mi * 16 + arow_off;
                ldsm4(a[mi][0], a[mi][1], a[mi][2], a[mi][3],
                      smb + OFF_AH + (uint32_t)row * 128 + (akb ^ (((uint32_t)row & 7) << 4)));
            }
            const uint32_t bkb = (uint32_t)(ks * 32 + bhalf * 16);
#pragma unroll
            for (int bi = 0; bi < 2; bi++) {
                const int row = warp_n * 32 + bi * 16 + brow_off;
                const uint32_t off = (uint32_t)row * 128 + (bkb ^ (((uint32_t)row & 7) << 4));
                uint32_t r0, r1, r2, r3;
                ldsm4(r0, r1, r2, r3, smb + OFF_B + off);
                bh[bi * 2][0] = r0;     bh[bi * 2][1] = r1;
                bh[bi * 2 + 1][0] = r2; bh[bi * 2 + 1][1] = r3;
                ldsm4(r0, r1, r2, r3, smb + OFF_B + 16384 + off);
                bl[bi * 2][0] = r0;     bl[bi * 2][1] = r1;
                bl[bi * 2 + 1][0] = r2; bl[bi * 2 + 1][1] = r3;
            }
#pragma unroll
            for (int mi = 0; mi < 4; mi++)
#pragma unroll
                for (int nj = 0; nj < 4; nj++) {
                    mma16816(acc[mi][nj], a[mi], bh[nj]);
                    mma16816(acc[mi][nj], a[mi], bl[nj]);
                }
#pragma unroll
            for (int mi = 0; mi < 4; mi++) {
                const int row = warp_m * 64 + mi * 16 + arow_off;
                ldsm4(a[mi][0], a[mi][1], a[mi][2], a[mi][3],
                      smb + OFF_AL + (uint32_t)row * 128 + (akb ^ (((uint32_t)row & 7) << 4)));
            }
#pragma unroll
            for (int mi = 0; mi < 4; mi++)
#pragma unroll
                for (int nj = 0; nj < 4; nj++)
                    mma16816(acc[mi][nj], a[mi], bh[nj]);
        }
        __syncthreads();
    }

    // ---- epilogue ----
    const int prow = l >> 2;
    const int pcol = (l & 3) * 2;
#pragma unroll
    for (int nj = 0; nj < 4; nj++) {
        const int co0 = warp_n * 32 + nj * 8 + pcol;
        const float b0 = __ldg(&bias[co0]);
        const float b1 = __ldg(&bias[co0 + 1]);
        float* o0 = out + ((size_t)(n * 128 + co0) << 14);
        float* o1 = out + ((size_t)(n * 128 + co0 + 1) << 14);
#pragma unroll
        for (int mi = 0; mi < 4; mi++) {
#pragma unroll
            for (int h = 0; h < 2; h++) {
                const int pix = warp_m * 64 + mi * 16 + prow + h * 8;
                const int oy = 2 * (2 * yt + (pix >> 6)) + py;
                const int ox = 2 * (pix & 63) + px;
                const int off = (oy << 7) + ox;
                o0[off] = acc[mi][nj][h * 2 + 0] + b0;
                o1[off] = acc[mi][nj][h * 2 + 1] + b1;
            }
        }
    }
}

extern "C" void kernel_launch(void* const* d_in, const int* in_sizes, int n_in,
                              void* d_out, int out_size) {
    const float* x    = (const float*)d_in[0];
    const float* w    = (const float*)d_in[1];
    const float* bias = (const float*)d_in[2];
    float* out        = (float*)d_out;

    cudaFuncSetAttribute(convt_mma, cudaFuncAttributeMaxDynamicSharedMemorySize, SMEM_BYTES);

    prep_wB<<<(1 << 20) / 256, 256>>>(w);

    dim3 grid(32, 4, 16);
    convt_mma<<<grid, 256, SMEM_BYTES>>>(x, bias, out);
}

// round 6
// speedup vs baseline: 4.4225x; 1.4619x over previous
#include <cuda_runtime.h>
#include <cuda_fp16.h>
#include <cstdint>

// ConvTranspose2d x(16,256,64,64) w(256,128,4,4) b(128) s=2 p=1 -> (16,128,128,128)
// Parity-class GEMM: D[pix=128, co=128] = A[pix, K=1024] * B[co, K]^T
// R6: fp16 2-pass — A = fp16(x), B = w split hi/lo fp16 (hh + hl), fp32 accum.
// cp.async staging, XS double-buffer prefetch, ldmatrix + mma.sync m16n8k16.f16.

#define NCHUNK 16
#define OFF_B  0                       // 32768: [w_hi 16K | w_lo 16K], pre-swizzled
#define OFF_A  32768                   // 16384: A fp16, swizzled 128B rows
#define OFF_XS 49152                   // 2 x 13824B: [cil16][r3][72 floats]
#define XS_ROW 72
#define XS_BUF_B 13824
#define SMEM_BYTES (49152 + 2 * XS_BUF_B)

__device__ __align__(1024) unsigned char g_wB[4][NCHUNK][2][16384];

__global__ void prep_wB(const float* __restrict__ w) {
    int idx = blockIdx.x * blockDim.x + threadIdx.x;
    if (idx >= (1 << 20)) return;
    int kq    = idx & 63;
    int co    = (idx >> 6) & 127;
    int part  = (idx >> 13) & 1;
    int chunk = (idx >> 14) & 15;
    int par   = idx >> 18;
    int py = par >> 1, px = par & 1;
    int cil = kq >> 2, ri = (kq >> 1) & 1, jx = kq & 1;
    int ci = chunk * 16 + cil;
    int ky = 3 - py - 2 * ri;
    int kx = 3 - px - 2 * jx;
    float v = w[((ci * 128 + co) * 4 + ky) * 4 + kx];
    __half hi = __float2half_rn(v);
    __half outv = (part == 0) ? hi : __float2half_rn(v - __half2float(hi));
    uint32_t off = (uint32_t)co * 128 + (uint32_t)kq * 2;
    uint32_t sw = off ^ ((off >> 3) & 0x70);
    *(__half*)(&g_wB[par][chunk][part][sw]) = outv;
}

__device__ __forceinline__ uint32_t smem_u32(const void* p) {
    uint32_t a;
    asm("{ .reg .u64 t; cvta.to.shared.u64 t, %1; cvt.u32.u64 %0, t; }" : "=r"(a) : "l"(p));
    return a;
}
__device__ __forceinline__ void cp16(uint32_t dst, const void* src, uint32_t srcsz) {
    asm volatile("cp.async.cg.shared.global [%0], [%1], 16, %2;"
                 :: "r"(dst), "l"(src), "r"(srcsz) : "memory");
}
__device__ __forceinline__ void ldsm4(uint32_t& r0, uint32_t& r1, uint32_t& r2, uint32_t& r3,
                                      uint32_t addr) {
    asm volatile("ldmatrix.sync.aligned.m8n8.x4.shared.b16 {%0,%1,%2,%3}, [%4];"
                 : "=r"(r0), "=r"(r1), "=r"(r2), "=r"(r3) : "r"(addr));
}
__device__ __forceinline__ void mma16816(float* c, const uint32_t* a, const uint32_t* b) {
    asm volatile(
        "mma.sync.aligned.m16n8k16.row.col.f32.f16.f16.f32 "
        "{%0,%1,%2,%3}, {%4,%5,%6,%7}, {%8,%9}, {%0,%1,%2,%3};"
        : "+f"(c[0]), "+f"(c[1]), "+f"(c[2]), "+f"(c[3])
        : "r"(a[0]), "r"(a[1]), "r"(a[2]), "r"(a[3]), "r"(b[0]), "r"(b[1]));
}

__global__ __launch_bounds__(256, 2)
void convt_mma(const float* __restrict__ x,
               const float* __restrict__ bias,
               float* __restrict__ out) {
    extern __shared__ char sm[];
    const int tid = threadIdx.x;
    const int l   = tid & 31;
    const int w   = tid >> 5;
    const int warp_m = w >> 2;
    const int warp_n = w & 3;
    const int yt  = blockIdx.x;
    const int par = blockIdx.y;
    const int n   = blockIdx.z;
    const int py = par >> 1, px = par & 1;

    const uint32_t smb = smem_u32(sm);
    float* XS0 = (float*)(sm + OFF_XS);

    // ---- prezero XS pad cols (both buffers): cols 0-3 and 68-71 ----
    for (int e = tid; e < 192; e += 256) {
        int side = e & 1, t = e >> 1;
        int r = t % 3, rem = t / 3;
        int cil = rem & 15, buf = rem >> 4;
        float4* p = (float4*)(XS0 + buf * (XS_BUF_B / 4) + (cil * 3 + r) * XS_ROW + side * 68);
        *p = make_float4(0.f, 0.f, 0.f, 0.f);
    }

    float acc[4][4][4];
#pragma unroll
    for (int mi = 0; mi < 4; mi++)
#pragma unroll
        for (int nj = 0; nj < 4; nj++)
#pragma unroll
            for (int q = 0; q < 4; q++) acc[mi][nj][q] = 0.0f;

    const int arow_off = (l & 7) + ((l >> 3) & 1) * 8;
    const int ahalf    = l >> 4;
    const int brow_off = (l & 7) + (l >> 4) * 8;
    const int bhalf    = (l >> 3) & 1;

    const int R = 2 * yt - 1 + py;
    const float* xb = x + (size_t)n * 256 * 4096;

    // ---- precomputed XS cp.async descriptors (3 per thread) ----
    uint32_t xs_dst[3], xs_fill[3];
    const float* xs_src[3];
#pragma unroll
    for (int j = 0; j < 3; j++) {
        int e = tid + j * 256;
        int i16 = e & 15, t = e >> 4;
        int r = t % 3, cil = t / 3;
        int iy = R + r;
        bool valid = (iy >= 0 && iy < 64);
        xs_fill[j] = valid ? 16u : 0u;
        int iyc = valid ? iy : 0;
        xs_src[j] = xb + ((size_t)cil << 12) + (iyc << 6) + i16 * 4;
        xs_dst[j] = (uint32_t)(((cil * 3 + r) * XS_ROW + 4 + i16 * 4) * 4);
    }

    // A-build mapping: thread -> (pixel, interleaved cil half)
    const int ap  = tid >> 1;
    const int akh = tid & 1;
    const int arp = ap >> 6, ax2 = ap & 63;
    const int ac0 = ax2 + px + 3;
    const uint32_t a_xorm = (uint32_t)(ap & 7) << 4;
    const uint32_t a_base = (uint32_t)ap * 128;

    // ---- prefetch XS[0] ----
#pragma unroll
    for (int j = 0; j < 3; j++)
        cp16(smb + OFF_XS + xs_dst[j], xs_src[j], xs_fill[j]);
    asm volatile("cp.async.commit_group;" ::: "memory");

    for (int c = 0; c < NCHUNK; c++) {
        const int buf = c & 1;
        asm volatile("cp.async.wait_group 0;" ::: "memory");   // XS[c] ready
        __syncthreads();

        // ---- issue B[c] (group), then XS[c+1] (group) ----
        {
            const char* bsrc = (const char*)g_wB[par][c] + tid * 16;
            const uint32_t bdst = smb + OFF_B + (uint32_t)tid * 16;
#pragma unroll
            for (int i = 0; i < 8; i++)
                cp16(bdst + i * 4096, bsrc + i * 4096, 16);
            asm volatile("cp.async.commit_group;" ::: "memory");
        }
        if (c + 1 < NCHUNK) {
            const size_t coff = (size_t)(c + 1) << 16;
            const uint32_t dst0 = smb + OFF_XS + (buf ^ 1) * XS_BUF_B;
#pragma unroll
            for (int j = 0; j < 3; j++)
                cp16(dst0 + xs_dst[j], xs_src[j] + coff, xs_fill[j]);
        }
        asm volatile("cp.async.commit_group;" ::: "memory");

        // ---- A build: im2col -> fp16, swizzled smem ----
        {
            const float* xsb = (const float*)(sm + OFF_XS + buf * XS_BUF_B);
#pragma unroll
            for (int q = 0; q < 8; q++) {
                const int cil = akh + 2 * q;
#pragma unroll
                for (int ri = 0; ri < 2; ri++) {
                    const float* row = xsb + (cil * 3 + arp + ri) * XS_ROW;
                    float v0 = row[ac0];
                    float v1 = row[ac0 + 1];
                    uint32_t hp;
                    asm("cvt.rn.f16x2.f32 %0, %1, %2;" : "=r"(hp) : "f"(v1), "f"(v0));
                    const uint32_t ao = a_base + (((uint32_t)(cil * 2 + ri) * 4) ^ a_xorm);
                    *(uint32_t*)(sm + OFF_A + ao) = hp;
                }
            }
        }
        asm volatile("cp.async.wait_group 1;" ::: "memory");   // B[c] ready
        __syncthreads();

        // ---- MMA: per ks load A, Bh, Bl -> A*Bh + A*Bl ----
#pragma unroll
        for (int ks = 0; ks < 4; ks++) {
            uint32_t a[4][4], bh[4][2], bl[4][2];
            const uint32_t akb = (uint32_t)(ks * 32 + ahalf * 16);
#pragma unroll
            for (int mi = 0; mi < 4; mi++) {
                const int row = warp_m * 64 + mi * 16 + arow_off;
                ldsm4(a[mi][0], a[mi][1], a[mi][2], a[mi][3],
                      smb + OFF_A + (uint32_t)row * 128 + (akb ^ (((uint32_t)row & 7) << 4)));
            }
            const uint32_t bkb = (uint32_t)(ks * 32 + bhalf * 16);
#pragma unroll
            for (int bi = 0; bi < 2; bi++) {
                const int row = warp_n * 32 + bi * 16 + brow_off;
                const uint32_t off = (uint32_t)row * 128 + (bkb ^ (((uint32_t)row & 7) << 4));
                uint32_t r0, r1, r2, r3;
                ldsm4(r0, r1, r2, r3, smb + OFF_B + off);
                bh[bi * 2][0] = r0;     bh[bi * 2][1] = r1;
                bh[bi * 2 + 1][0] = r2; bh[bi * 2 + 1][1] = r3;
                ldsm4(r0, r1, r2, r3, smb + OFF_B + 16384 + off);
                bl[bi * 2][0] = r0;     bl[bi * 2][1] = r1;
                bl[bi * 2 + 1][0] = r2; bl[bi * 2 + 1][1] = r3;
            }
#pragma unroll
            for (int mi = 0; mi < 4; mi++)
#pragma unroll
                for (int nj = 0; nj < 4; nj++) {
                    mma16816(acc[mi][nj], a[mi], bh[nj]);
                    mma16816(acc[mi][nj], a[mi], bl[nj]);
                }
        }
        __syncthreads();
    }

    // ---- epilogue ----
    const int prow = l >> 2;
    const int pcol = (l & 3) * 2;
#pragma unroll
    for (int nj = 0; nj < 4; nj++) {
        const int co0 = warp_n * 32 + nj * 8 + pcol;
        const float b0 = __ldg(&bias[co0]);
        const float b1 = __ldg(&bias[co0 + 1]);
        float* o0 = out + ((size_t)(n * 128 + co0) << 14);
        float* o1 = out + ((size_t)(n * 128 + co0 + 1) << 14);
#pragma unroll
        for (int mi = 0; mi < 4; mi++) {
#pragma unroll
            for (int h = 0; h < 2; h++) {
                const int pix = warp_m * 64 + mi * 16 + prow + h * 8;
                const int oy = 2 * (2 * yt + (pix >> 6)) + py;
                const int ox = 2 * (pix & 63) + px;
                const int off = (oy << 7) + ox;
                o0[off] = acc[mi][nj][h * 2 + 0] + b0;
                o1[off] = acc[mi][nj][h * 2 + 1] + b1;
            }
        }
    }
}

extern "C" void kernel_launch(void* const* d_in, const int* in_sizes, int n_in,
                              void* d_out, int out_size) {
    const float* x    = (const float*)d_in[0];
    const float* w    = (const float*)d_in[1];
    const float* bias = (const float*)d_in[2];
    float* out        = (float*)d_out;

    cudaFuncSetAttribute(convt_mma, cudaFuncAttributeMaxDynamicSharedMemorySize, SMEM_BYTES);

    prep_wB<<<(1 << 20) / 256, 256>>>(w);

    dim3 grid(32, 4, 16);
    convt_mma<<<grid, 256, SMEM_BYTES>>>(x, bias, out);
}

// round 7
// speedup vs baseline: 6.0861x; 1.3762x over previous
#include <cuda_runtime.h>
#include <cuda_fp16.h>
#include <cstdint>

// ConvTranspose2d x(16,256,64,64) w(256,128,4,4) b(128) s=2 p=1 -> (16,128,128,128)
// Parity-class GEMM: D[pix=128, co=128] = A[pix, K=1024] * B[co, K]^T
// R7: single-pass fp16 (A = fp16(x), B = fp16(w)), fp32 accum.
// cp.async staging, XS double-buffer prefetch, ldmatrix + mma.sync m16n8k16.f16.

#define NCHUNK 16
#define OFF_B  0                       // 16384: w fp16, pre-swizzled 128B rows
#define OFF_A  16384                   // 16384: A fp16, swizzled 128B rows
#define OFF_XS 32768                   // 2 x 13824B: [cil16][r3][72 floats]
#define XS_ROW 72
#define XS_BUF_B 13824
#define SMEM_BYTES (32768 + 2 * XS_BUF_B)

__device__ __align__(1024) unsigned char g_wB[4][NCHUNK][16384];

__global__ void prep_wB(const float* __restrict__ w) {
    int idx = blockIdx.x * blockDim.x + threadIdx.x;
    if (idx >= (1 << 19)) return;
    int kq    = idx & 63;
    int co    = (idx >> 6) & 127;
    int chunk = (idx >> 13) & 15;
    int par   = idx >> 17;
    int py = par >> 1, px = par & 1;
    int cil = kq >> 2, ri = (kq >> 1) & 1, jx = kq & 1;
    int ci = chunk * 16 + cil;
    int ky = 3 - py - 2 * ri;
    int kx = 3 - px - 2 * jx;
    float v = w[((ci * 128 + co) * 4 + ky) * 4 + kx];
    uint32_t off = (uint32_t)co * 128 + (uint32_t)kq * 2;
    uint32_t sw = off ^ ((off >> 3) & 0x70);
    *(__half*)(&g_wB[par][chunk][sw]) = __float2half_rn(v);
}

__device__ __forceinline__ uint32_t smem_u32(const void* p) {
    uint32_t a;
    asm("{ .reg .u64 t; cvta.to.shared.u64 t, %1; cvt.u32.u64 %0, t; }" : "=r"(a) : "l"(p));
    return a;
}
__device__ __forceinline__ void cp16(uint32_t dst, const void* src, uint32_t srcsz) {
    asm volatile("cp.async.cg.shared.global [%0], [%1], 16, %2;"
                 :: "r"(dst), "l"(src), "r"(srcsz) : "memory");
}
__device__ __forceinline__ void ldsm4(uint32_t& r0, uint32_t& r1, uint32_t& r2, uint32_t& r3,
                                      uint32_t addr) {
    asm volatile("ldmatrix.sync.aligned.m8n8.x4.shared.b16 {%0,%1,%2,%3}, [%4];"
                 : "=r"(r0), "=r"(r1), "=r"(r2), "=r"(r3) : "r"(addr));
}
__device__ __forceinline__ void mma16816(float* c, const uint32_t* a, const uint32_t* b) {
    asm volatile(
        "mma.sync.aligned.m16n8k16.row.col.f32.f16.f16.f32 "
        "{%0,%1,%2,%3}, {%4,%5,%6,%7}, {%8,%9}, {%0,%1,%2,%3};"
        : "+f"(c[0]), "+f"(c[1]), "+f"(c[2]), "+f"(c[3])
        : "r"(a[0]), "r"(a[1]), "r"(a[2]), "r"(a[3]), "r"(b[0]), "r"(b[1]));
}

__global__ __launch_bounds__(256, 2)
void convt_mma(const float* __restrict__ x,
               const float* __restrict__ bias,
               float* __restrict__ out) {
    extern __shared__ char sm[];
    const int tid = threadIdx.x;
    const int l   = tid & 31;
    const int w   = tid >> 5;
    const int warp_m = w >> 2;
    const int warp_n = w & 3;
    const int yt  = blockIdx.x;
    const int par = blockIdx.y;
    const int n   = blockIdx.z;
    const int py = par >> 1, px = par & 1;

    const uint32_t smb = smem_u32(sm);
    float* XS0 = (float*)(sm + OFF_XS);

    // ---- prezero XS pad cols (both buffers): cols 0-3 and 68-71 ----
    for (int e = tid; e < 192; e += 256) {
        int side = e & 1, t = e >> 1;
        int r = t % 3, rem = t / 3;
        int cil = rem & 15, buf = rem >> 4;
        float4* p = (float4*)(XS0 + buf * (XS_BUF_B / 4) + (cil * 3 + r) * XS_ROW + side * 68);
        *p = make_float4(0.f, 0.f, 0.f, 0.f);
    }

    float acc[4][4][4];
#pragma unroll
    for (int mi = 0; mi < 4; mi++)
#pragma unroll
        for (int nj = 0; nj < 4; nj++)
#pragma unroll
            for (int q = 0; q < 4; q++) acc[mi][nj][q] = 0.0f;

    const int arow_off = (l & 7) + ((l >> 3) & 1) * 8;
    const int ahalf    = l >> 4;
    const int brow_off = (l & 7) + (l >> 4) * 8;
    const int bhalf    = (l >> 3) & 1;

    const int R = 2 * yt - 1 + py;
    const float* xb = x + (size_t)n * 256 * 4096;

    // ---- precomputed XS cp.async descriptors (3 per thread) ----
    uint32_t xs_dst[3], xs_fill[3];
    const float* xs_src[3];
#pragma unroll
    for (int j = 0; j < 3; j++) {
        int e = tid + j * 256;
        int i16 = e & 15, t = e >> 4;
        int r = t % 3, cil = t / 3;
        int iy = R + r;
        bool valid = (iy >= 0 && iy < 64);
        xs_fill[j] = valid ? 16u : 0u;
        int iyc = valid ? iy : 0;
        xs_src[j] = xb + ((size_t)cil << 12) + (iyc << 6) + i16 * 4;
        xs_dst[j] = (uint32_t)(((cil * 3 + r) * XS_ROW + 4 + i16 * 4) * 4);
    }

    // A-build mapping: thread -> (pixel, interleaved cil half)
    const int ap  = tid >> 1;
    const int akh = tid & 1;
    const int arp = ap >> 6, ax2 = ap & 63;
    const int ac0 = ax2 + px + 3;
    const uint32_t a_xorm = (uint32_t)(ap & 7) << 4;
    const uint32_t a_base = (uint32_t)ap * 128;

    // ---- prefetch XS[0] ----
#pragma unroll
    for (int j = 0; j < 3; j++)
        cp16(smb + OFF_XS + xs_dst[j], xs_src[j], xs_fill[j]);
    asm volatile("cp.async.commit_group;" ::: "memory");

    for (int c = 0; c < NCHUNK; c++) {
        const int buf = c & 1;
        asm volatile("cp.async.wait_group 0;" ::: "memory");   // XS[c] ready
        __syncthreads();

        // ---- issue B[c] (group), then XS[c+1] (group) ----
        {
            const char* bsrc = (const char*)g_wB[par][c] + tid * 16;
            const uint32_t bdst = smb + OFF_B + (uint32_t)tid * 16;
#pragma unroll
            for (int i = 0; i < 4; i++)
                cp16(bdst + i * 4096, bsrc + i * 4096, 16);
            asm volatile("cp.async.commit_group;" ::: "memory");
        }
        if (c + 1 < NCHUNK) {
            const size_t coff = (size_t)(c + 1) << 16;
            const uint32_t dst0 = smb + OFF_XS + (buf ^ 1) * XS_BUF_B;
#pragma unroll
            for (int j = 0; j < 3; j++)
                cp16(dst0 + xs_dst[j], xs_src[j] + coff, xs_fill[j]);
        }
        asm volatile("cp.async.commit_group;" ::: "memory");

        // ---- A build: im2col -> fp16, swizzled smem ----
        {
            const float* xsb = (const float*)(sm + OFF_XS + buf * XS_BUF_B);
#pragma unroll
            for (int q = 0; q < 8; q++) {
                const int cil = akh + 2 * q;
#pragma unroll
                for (int ri = 0; ri < 2; ri++) {
                    const float* row = xsb + (cil * 3 + arp + ri) * XS_ROW;
                    float v0 = row[ac0];
                    float v1 = row[ac0 + 1];
                    uint32_t hp;
                    asm("cvt.rn.f16x2.f32 %0, %1, %2;" : "=r"(hp) : "f"(v1), "f"(v0));
                    const uint32_t ao = a_base + (((uint32_t)(cil * 2 + ri) * 4) ^ a_xorm);
                    *(uint32_t*)(sm + OFF_A + ao) = hp;
                }
            }
        }
        asm volatile("cp.async.wait_group 1;" ::: "memory");   // B[c] ready
        __syncthreads();

        // ---- MMA ----
#pragma unroll
        for (int ks = 0; ks < 4; ks++) {
            uint32_t a[4][4], b[4][2];
            const uint32_t akb = (uint32_t)(ks * 32 + ahalf * 16);
#pragma unroll
            for (int mi = 0; mi < 4; mi++) {
                const int row = warp_m * 64 + mi * 16 + arow_off;
                ldsm4(a[mi][0], a[mi][1], a[mi][2], a[mi][3],
                      smb + OFF_A + (uint32_t)row * 128 + (akb ^ (((uint32_t)row & 7) << 4)));
            }
            const uint32_t bkb = (uint32_t)(ks * 32 + bhalf * 16);
#pragma unroll
            for (int bi = 0; bi < 2; bi++) {
                const int row = warp_n * 32 + bi * 16 + brow_off;
                const uint32_t off = (uint32_t)row * 128 + (bkb ^ (((uint32_t)row & 7) << 4));
                uint32_t r0, r1, r2, r3;
                ldsm4(r0, r1, r2, r3, smb + OFF_B + off);
                b[bi * 2][0] = r0;     b[bi * 2][1] = r1;
                b[bi * 2 + 1][0] = r2; b[bi * 2 + 1][1] = r3;
            }
#pragma unroll
            for (int mi = 0; mi < 4; mi++)
#pragma unroll
                for (int nj = 0; nj < 4; nj++)
                    mma16816(acc[mi][nj], a[mi], b[nj]);
        }
        __syncthreads();
    }

    // ---- epilogue ----
    const int prow = l >> 2;
    const int pcol = (l & 3) * 2;
#pragma unroll
    for (int nj = 0; nj < 4; nj++) {
        const int co0 = warp_n * 32 + nj * 8 + pcol;
        const float b0 = __ldg(&bias[co0]);
        const float b1 = __ldg(&bias[co0 + 1]);
        float* o0 = out + ((size_t)(n * 128 + co0) << 14);
        float* o1 = out + ((size_t)(n * 128 + co0 + 1) << 14);
#pragma unroll
        for (int mi = 0; mi < 4; mi++) {
#pragma unroll
            for (int h = 0; h < 2; h++) {
                const int pix = warp_m * 64 + mi * 16 + prow + h * 8;
                const int oy = 2 * (2 * yt + (pix >> 6)) + py;
                const int ox = 2 * (pix & 63) + px;
                const int off = (oy << 7) + ox;
                o0[off] = acc[mi][nj][h * 2 + 0] + b0;
                o1[off] = acc[mi][nj][h * 2 + 1] + b1;
            }
        }
    }
}

extern "C" void kernel_launch(void* const* d_in, const int* in_sizes, int n_in,
                              void* d_out, int out_size) {
    const float* x    = (const float*)d_in[0];
    const float* w    = (const float*)d_in[1];
    const float* bias = (const float*)d_in[2];
    float* out        = (float*)d_out;

    cudaFuncSetAttribute(convt_mma, cudaFuncAttributeMaxDynamicSharedMemorySize, SMEM_BYTES);

    prep_wB<<<(1 << 19) / 256, 256>>>(w);

    dim3 grid(32, 4, 16);
    convt_mma<<<grid, 256, SMEM_BYTES>>>(x, bias, out);
}